// round 14
// baseline (speedup 1.0000x reference)
#include <cuda_runtime.h>
#include <cstdint>

// y[e, o] = sum_i weight[weight_idx[e], o, i] * values[input_idx[e], i]
// E = 1M, D = 16, N_W = 1024.
//
// Pipeline (4 kernels):
//   A) per-block smem histogram of weight_idx; writes packed u32 (w<<12 | rank)
//   B) segmented column scan over block histograms
//   C) in-block bin scan + atomic-free scatter of {e, input_idx}
//   D) compute: grid 512, TWO weights per CTA (perfect single wave, halved
//      relative bin-size variance). Per weight: 16 lanes per edge, weight rows
//      in regs, software-pipelined 2 tiles deep (pe prefetch + reg-buffered
//      gathers), conflict-free stride-16 smem, direct STG.32 stores.

#define D 16
#define NW_MAX 1024
#define PERM_CAP (1 << 21)
#define B_SORT 1184
#define T_SORT 256
#define NSEG 8
#define SEG_B ((B_SORT + NSEG - 1) / NSEG)   // 148
#define CGRID 512                            // compute CTAs (2 weights each)

__device__ int      g_bhist  [B_SORT * NW_MAX];
__device__ int      g_bstart [B_SORT * NW_MAX];
__device__ int      g_segsum [NSEG * NW_MAX];
__device__ int      g_tot    [NW_MAX];
__device__ int      g_offsets[NW_MAX];
__device__ unsigned g_wrank[PERM_CAP];        // (w << 12) | rank
__device__ int2     g_pe   [PERM_CAP];        // {edge id, input_idx}

// ---------------- Pass A: histogram + packed (w,rank) -----------------------

__global__ __launch_bounds__(T_SORT) void passA_hist(
    const int* __restrict__ weight_idx, int E, int chunk)
{
    __shared__ int h[NW_MAX];
    const int b = blockIdx.x;
    for (int i = threadIdx.x; i < NW_MAX; i += T_SORT) h[i] = 0;
    __syncthreads();

    const int lo = b * chunk;
    const int hi = min(lo + chunk, E);
    for (int e = lo + threadIdx.x; e < hi; e += T_SORT) {
        const int w = weight_idx[e];
        const int r = atomicAdd(&h[w], 1);                 // smem only
        g_wrank[e] = ((unsigned)w << 12) | (unsigned)r;    // coalesced 4B
    }
    __syncthreads();

    for (int i = threadIdx.x; i < NW_MAX; i += T_SORT)
        g_bhist[b * NW_MAX + i] = h[i];
}

// ------------- Pass B: segmented column scan over blocks (per bin) ----------

__global__ void passB_colscan(int nblocks)
{
    const int w   = blockIdx.x * blockDim.x + threadIdx.x;
    const int seg = blockIdx.y;
    if (w >= NW_MAX) return;
    const int b0 = seg * SEG_B;
    const int b1 = min(b0 + SEG_B, nblocks);
    int run = 0;
    for (int b = b0; b < b1; b++) {
        const int c = g_bhist[b * NW_MAX + w];   // coalesced across w
        g_bstart[b * NW_MAX + w] = run;
        run += c;
    }
    g_segsum[seg * NW_MAX + w] = run;
}

// ------- Pass C: in-block bin scan + atomic-free scatter --------------------

__global__ __launch_bounds__(T_SORT) void passC_scan_scatter(
    const int* __restrict__ input_idx, int E, int chunk)
{
    __shared__ int cur  [NW_MAX];
    __shared__ int spart[T_SORT];

    const int b   = blockIdx.x;
    const int seg = b / SEG_B;
    const int tid = threadIdx.x;
    const int w0  = tid * 4;                 // this thread's 4 bins

    int tot[4], segb[4];
#pragma unroll
    for (int q = 0; q < 4; q++) { tot[q] = 0; segb[q] = 0; }
#pragma unroll
    for (int g = 0; g < NSEG; g++) {
#pragma unroll
        for (int q = 0; q < 4; q++) {
            const int v = g_segsum[g * NW_MAX + w0 + q];   // coalesced
            if (g < seg) segb[q] += v;
            tot[q] += v;
        }
    }
    const int lsum = tot[0] + tot[1] + tot[2] + tot[3];
    spart[tid] = lsum;
    __syncthreads();

    int run = lsum;
#pragma unroll
    for (int off = 1; off < T_SORT; off <<= 1) {
        const int add = (tid >= off) ? spart[tid - off] : 0;
        __syncthreads();
        spart[tid] = run = run + add;
        __syncthreads();
    }
    const int excl = run - lsum;

    int off_q[4];
    off_q[0] = excl;
    off_q[1] = off_q[0] + tot[0];
    off_q[2] = off_q[1] + tot[1];
    off_q[3] = off_q[2] + tot[2];
#pragma unroll
    for (int q = 0; q < 4; q++) {
        const int w = w0 + q;
        cur[w] = off_q[q] + segb[q] + g_bstart[b * NW_MAX + w];
        if (b == 0) {
            g_offsets[w] = off_q[q];
            g_tot[w]     = tot[q];
        }
    }
    __syncthreads();

    const int lo = b * chunk;
    const int hi = min(lo + chunk, E);
    for (int e = lo + tid; e < hi; e += T_SORT) {
        const unsigned v = g_wrank[e];            // coalesced, independent
        const int ii     = input_idx[e];          // coalesced, independent
        const int w      = (int)(v >> 12);
        const int rk     = (int)(v & 0xFFFu);
        const int p      = cur[w] + rk;           // LDS, no atomics
        g_pe[p] = make_int2(e, ii);               // single 8B store
    }
}

// ------------- Compute: 2 weights per CTA, pipelined, 16 lanes/edge ---------

#define MATVEC16(ACC, WR, X0, X1, X2, X3)                     \
    do {                                                      \
        ACC =            WR[0]  * X0.x;                       \
        ACC = fmaf(WR[1],  X0.y, ACC);                        \
        ACC = fmaf(WR[2],  X0.z, ACC);                        \
        ACC = fmaf(WR[3],  X0.w, ACC);                        \
        ACC = fmaf(WR[4],  X1.x, ACC);                        \
        ACC = fmaf(WR[5],  X1.y, ACC);                        \
        ACC = fmaf(WR[6],  X1.z, ACC);                        \
        ACC = fmaf(WR[7],  X1.w, ACC);                        \
        ACC = fmaf(WR[8],  X2.x, ACC);                        \
        ACC = fmaf(WR[9],  X2.y, ACC);                        \
        ACC = fmaf(WR[10], X2.z, ACC);                        \
        ACC = fmaf(WR[11], X2.w, ACC);                        \
        ACC = fmaf(WR[12], X3.x, ACC);                        \
        ACC = fmaf(WR[13], X3.y, ACC);                        \
        ACC = fmaf(WR[14], X3.z, ACC);                        \
        ACC = fmaf(WR[15], X3.w, ACC);                        \
    } while (0)

__device__ __forceinline__ void process_weight(
    const float* __restrict__ values,
    const float* __restrict__ weight,
    float* __restrict__ out,
    float* myx, int w, int warpId, int wl, int half, int l16)
{
    float wr[D];
    {
        const float4* wr4 = reinterpret_cast<const float4*>(
            weight + (size_t)w * (D * D) + l16 * D);
        const float4 a = __ldg(&wr4[0]);
        const float4 b = __ldg(&wr4[1]);
        const float4 c = __ldg(&wr4[2]);
        const float4 d = __ldg(&wr4[3]);
        wr[0]=a.x;  wr[1]=a.y;  wr[2]=a.z;  wr[3]=a.w;
        wr[4]=b.x;  wr[5]=b.y;  wr[6]=b.z;  wr[7]=b.w;
        wr[8]=c.x;  wr[9]=c.y;  wr[10]=c.z; wr[11]=c.w;
        wr[12]=d.x; wr[13]=d.y; wr[14]=d.z; wr[15]=d.w;
    }

    const int start = g_offsets[w];
    const int count = g_tot[w];

    const int b0 = warpId * 32;
    const int nfull = (count >= b0 + 32) ? ((count - b0 - 32) / 256 + 1) : 0;
    const int pbase = b0 + nfull * 256;

    if (nfull > 0) {
        int2 pe_cur, pe_nxt, pe_fut;
        pe_cur = g_pe[start + b0 + wl];

        {
            float gx[16];
#pragma unroll
            for (int k = 0; k < 16; k++) {
                const int s  = 2 * k + half;
                const int ii = __shfl_sync(0xFFFFFFFFu, pe_cur.y, s);
                gx[k] = __ldg(&values[(size_t)ii * D + l16]);
            }
            if (nfull > 1) pe_nxt = g_pe[start + b0 + 256 + wl];
#pragma unroll
            for (int k = 0; k < 16; k++)
                myx[(2 * k + half) * D + l16] = gx[k];
        }
        __syncwarp();

        for (int j = 0; j < nfull; j++) {
            const bool hasN = (j + 1 < nfull);
            if (j + 2 < nfull) pe_fut = g_pe[start + b0 + (j + 2) * 256 + wl];

            float gx[16];
            if (hasN) {
#pragma unroll
                for (int k = 0; k < 16; k++) {
                    const int s  = 2 * k + half;
                    const int ii = __shfl_sync(0xFFFFFFFFu, pe_nxt.y, s);
                    gx[k] = __ldg(&values[(size_t)ii * D + l16]);
                }
            }

#pragma unroll
            for (int k = 0; k < 16; k++) {
                const int s = 2 * k + half;
                const float4* xr = reinterpret_cast<const float4*>(myx + s * D);
                const float4 x0 = xr[0];
                const float4 x1 = xr[1];
                const float4 x2 = xr[2];
                const float4 x3 = xr[3];
                float acc;
                MATVEC16(acc, wr, x0, x1, x2, x3);
                const int e = __shfl_sync(0xFFFFFFFFu, pe_cur.x, s);
                out[(size_t)e * D + l16] = acc;
            }
            __syncwarp();

            if (hasN) {
#pragma unroll
                for (int k = 0; k < 16; k++)
                    myx[(2 * k + half) * D + l16] = gx[k];
            }
            __syncwarp();

            pe_cur = pe_nxt;
            pe_nxt = pe_fut;
        }
    }

    if (pbase < count) {
        const int nvalid = count - pbase;        // 1..31
        const int r = pbase + wl;
        const int2 pe = (r < count) ? g_pe[start + r] : make_int2(0, 0);

#pragma unroll
        for (int k = 0; k < 16; k++) {
            const int s  = 2 * k + half;
            const int ss = (s < nvalid) ? s : 0;
            const int ii = __shfl_sync(0xFFFFFFFFu, pe.y, ss);
            myx[s * D + l16] = __ldg(&values[(size_t)ii * D + l16]);
        }
        __syncwarp();

#pragma unroll
        for (int k = 0; k < 16; k++) {
            const int s  = 2 * k + half;
            const int ss = (s < nvalid) ? s : 0;
            const int e  = __shfl_sync(0xFFFFFFFFu, pe.x, ss);
            const float4* xr = reinterpret_cast<const float4*>(myx + s * D);
            const float4 x0 = xr[0];
            const float4 x1 = xr[1];
            const float4 x2 = xr[2];
            const float4 x3 = xr[3];
            float acc;
            MATVEC16(acc, wr, x0, x1, x2, x3);
            if (s < nvalid) out[(size_t)e * D + l16] = acc;
        }
        __syncwarp();
    }
}

__global__ __launch_bounds__(256, 4) void compute_sorted_kernel(
    const float* __restrict__ values,   // [N_POOL, 16]
    const float* __restrict__ weight,   // [N_W, 16, 16] row-major
    float* __restrict__ out)            // [E, 16]
{
    __shared__ float sx[8][32 * D];     // 16 KB; paired rows conflict-free

    const int tid    = threadIdx.x;
    const int warpId = tid >> 5;
    const int wl     = tid & 31;
    const int half   = wl >> 4;
    const int l16    = wl & 15;
    float* myx = sx[warpId];

    // two weights per CTA -> single balanced wave (512 CTAs at 4/SM)
    process_weight(values, weight, out, myx, blockIdx.x,
                   warpId, wl, half, l16);
    process_weight(values, weight, out, myx, blockIdx.x + CGRID,
                   warpId, wl, half, l16);
}

// ---------------- fallback (R1 kernel) for unexpected shapes ----------------

__global__ __launch_bounds__(256) void edge_linear_fallback(
    const float* __restrict__ values,
    const float4* __restrict__ weight4,
    const int* __restrict__ input_idx,
    const int* __restrict__ weight_idx,
    float* __restrict__ out, int E)
{
    const int gtid = blockIdx.x * blockDim.x + threadIdx.x;
    const int edge = gtid >> 4;
    const int lane = threadIdx.x & 15;
    if (edge >= E) return;

    const int ii = __ldg(&input_idx[edge]);
    const int wi = __ldg(&weight_idx[edge]);
    const float xl = __ldg(&values[(size_t)ii * D + lane]);

    const float4* wrp = weight4 + (size_t)wi * (D * D / 4) + lane * 4;
    const float4 a = __ldg(&wrp[0]);
    const float4 b = __ldg(&wrp[1]);
    const float4 c = __ldg(&wrp[2]);
    const float4 d = __ldg(&wrp[3]);
    const float wrow[D] = {a.x, a.y, a.z, a.w,
                           b.x, b.y, b.z, b.w,
                           c.x, c.y, c.z, c.w,
                           d.x, d.y, d.z, d.w};

    float acc = 0.0f;
#pragma unroll
    for (int i = 0; i < D; i++)
        acc = fmaf(wrow[i], __shfl_sync(0xFFFFFFFFu, xl, i, 16), acc);

    out[(size_t)edge * D + lane] = acc;
}

extern "C" void kernel_launch(void* const* d_in, const int* in_sizes, int n_in,
                              void* d_out, int out_size)
{
    const float* values     = (const float*)d_in[0];
    const float* weight     = (const float*)d_in[1];
    const int*   input_idx  = (const int*)d_in[2];
    const int*   weight_idx = (const int*)d_in[3];
    float*       out        = (float*)d_out;

    const int E  = in_sizes[2];
    const int NW = in_sizes[1] / (D * D);

    const int chunk = (E + B_SORT - 1) / B_SORT;

    // rank must fit 12 bits of the packed word
    if (NW != NW_MAX || E > PERM_CAP || chunk > 4095) {
        const int threads = 256;
        const long long total = (long long)E * 16;
        edge_linear_fallback<<<(int)((total + threads - 1) / threads), threads>>>(
            values, (const float4*)weight, input_idx, weight_idx, out, E);
        return;
    }

    passA_hist        <<<B_SORT, T_SORT>>>(weight_idx, E, chunk);
    passB_colscan     <<<dim3(NW_MAX / 256, NSEG), 256>>>(B_SORT);
    passC_scan_scatter<<<B_SORT, T_SORT>>>(input_idx, E, chunk);
    compute_sorted_kernel<<<CGRID, 256>>>(values, weight, out);
}

// round 15
// speedup vs baseline: 1.1857x; 1.1857x over previous
#include <cuda_runtime.h>
#include <cstdint>

// y[e, o] = sum_i weight[weight_idx[e], o, i] * values[input_idx[e], i]
// E = 1M, D = 16, N_W = 1024.
//
// Pipeline (4 kernels):
//   A) per-block smem histogram of weight_idx; writes packed u32 (w<<12 | rank)
//   B) segmented column scan over block histograms
//   C) in-block bin scan + atomic-free scatter of {e, input_idx}
//   D) compute: grid 2048, each CTA does HALF of one bin (~488 edges) ->
//      fine-grained scheduling, ~7% worst-case tail. Per bin-half: 16 lanes
//      per edge, weight rows in regs, software-pipelined 2 tiles deep,
//      conflict-free stride-16 smem, direct STG.32 stores.

#define D 16
#define NW_MAX 1024
#define PERM_CAP (1 << 21)
#define B_SORT 592                           // one full wave at 4 CTAs/SM
#define T_SORT 256
#define NSEG 8
#define SEG_B ((B_SORT + NSEG - 1) / NSEG)   // 74

__device__ int      g_bhist  [B_SORT * NW_MAX];
__device__ int      g_bstart [B_SORT * NW_MAX];
__device__ int      g_segsum [NSEG * NW_MAX];
__device__ int      g_tot    [NW_MAX];
__device__ int      g_offsets[NW_MAX];
__device__ unsigned g_wrank[PERM_CAP];        // (w << 12) | rank
__device__ int2     g_pe   [PERM_CAP];        // {edge id, input_idx}

// ---------------- Pass A: histogram + packed (w,rank) -----------------------

__global__ __launch_bounds__(T_SORT) void passA_hist(
    const int* __restrict__ weight_idx, int E, int chunk)
{
    __shared__ int h[NW_MAX];
    const int b = blockIdx.x;
    for (int i = threadIdx.x; i < NW_MAX; i += T_SORT) h[i] = 0;
    __syncthreads();

    const int lo = b * chunk;
    const int hi = min(lo + chunk, E);
    for (int e = lo + threadIdx.x; e < hi; e += T_SORT) {
        const int w = weight_idx[e];
        const int r = atomicAdd(&h[w], 1);                 // smem only
        g_wrank[e] = ((unsigned)w << 12) | (unsigned)r;    // coalesced 4B
    }
    __syncthreads();

    for (int i = threadIdx.x; i < NW_MAX; i += T_SORT)
        g_bhist[b * NW_MAX + i] = h[i];
}

// ------------- Pass B: segmented column scan over blocks (per bin) ----------

__global__ void passB_colscan(int nblocks)
{
    const int w   = blockIdx.x * blockDim.x + threadIdx.x;
    const int seg = blockIdx.y;
    if (w >= NW_MAX) return;
    const int b0 = seg * SEG_B;
    const int b1 = min(b0 + SEG_B, nblocks);
    int run = 0;
    for (int b = b0; b < b1; b++) {
        const int c = g_bhist[b * NW_MAX + w];   // coalesced across w
        g_bstart[b * NW_MAX + w] = run;
        run += c;
    }
    g_segsum[seg * NW_MAX + w] = run;
}

// ------- Pass C: in-block bin scan + atomic-free scatter --------------------

__global__ __launch_bounds__(T_SORT) void passC_scan_scatter(
    const int* __restrict__ input_idx, int E, int chunk)
{
    __shared__ int cur  [NW_MAX];
    __shared__ int spart[T_SORT];

    const int b   = blockIdx.x;
    const int seg = b / SEG_B;
    const int tid = threadIdx.x;
    const int w0  = tid * 4;                 // this thread's 4 bins

    int tot[4], segb[4];
#pragma unroll
    for (int q = 0; q < 4; q++) { tot[q] = 0; segb[q] = 0; }
#pragma unroll
    for (int g = 0; g < NSEG; g++) {
#pragma unroll
        for (int q = 0; q < 4; q++) {
            const int v = g_segsum[g * NW_MAX + w0 + q];   // coalesced
            if (g < seg) segb[q] += v;
            tot[q] += v;
        }
    }
    const int lsum = tot[0] + tot[1] + tot[2] + tot[3];
    spart[tid] = lsum;
    __syncthreads();

    int run = lsum;
#pragma unroll
    for (int off = 1; off < T_SORT; off <<= 1) {
        const int add = (tid >= off) ? spart[tid - off] : 0;
        __syncthreads();
        spart[tid] = run = run + add;
        __syncthreads();
    }
    const int excl = run - lsum;

    int off_q[4];
    off_q[0] = excl;
    off_q[1] = off_q[0] + tot[0];
    off_q[2] = off_q[1] + tot[1];
    off_q[3] = off_q[2] + tot[2];
#pragma unroll
    for (int q = 0; q < 4; q++) {
        const int w = w0 + q;
        cur[w] = off_q[q] + segb[q] + g_bstart[b * NW_MAX + w];
        if (b == 0) {
            g_offsets[w] = off_q[q];
            g_tot[w]     = tot[q];
        }
    }
    __syncthreads();

    const int lo = b * chunk;
    const int hi = min(lo + chunk, E);
    for (int e = lo + tid; e < hi; e += T_SORT) {
        const unsigned v = g_wrank[e];            // coalesced, independent
        const int ii     = input_idx[e];          // coalesced, independent
        const int w      = (int)(v >> 12);
        const int rk     = (int)(v & 0xFFFu);
        const int p      = cur[w] + rk;           // LDS, no atomics
        g_pe[p] = make_int2(e, ii);               // single 8B store
    }
}

// ------------- Compute: half-bin per CTA, pipelined, 16 lanes/edge ----------

#define MATVEC16(ACC, WR, X0, X1, X2, X3)                     \
    do {                                                      \
        ACC =            WR[0]  * X0.x;                       \
        ACC = fmaf(WR[1],  X0.y, ACC);                        \
        ACC = fmaf(WR[2],  X0.z, ACC);                        \
        ACC = fmaf(WR[3],  X0.w, ACC);                        \
        ACC = fmaf(WR[4],  X1.x, ACC);                        \
        ACC = fmaf(WR[5],  X1.y, ACC);                        \
        ACC = fmaf(WR[6],  X1.z, ACC);                        \
        ACC = fmaf(WR[7],  X1.w, ACC);                        \
        ACC = fmaf(WR[8],  X2.x, ACC);                        \
        ACC = fmaf(WR[9],  X2.y, ACC);                        \
        ACC = fmaf(WR[10], X2.z, ACC);                        \
        ACC = fmaf(WR[11], X2.w, ACC);                        \
        ACC = fmaf(WR[12], X3.x, ACC);                        \
        ACC = fmaf(WR[13], X3.y, ACC);                        \
        ACC = fmaf(WR[14], X3.z, ACC);                        \
        ACC = fmaf(WR[15], X3.w, ACC);                        \
    } while (0)

__global__ __launch_bounds__(256, 4) void compute_sorted_kernel(
    const float* __restrict__ values,   // [N_POOL, 16]
    const float* __restrict__ weight,   // [N_W, 16, 16] row-major
    float* __restrict__ out)            // [E, 16]
{
    __shared__ float sx[8][32 * D];     // 16 KB; paired rows conflict-free

    const int tid    = threadIdx.x;
    const int warpId = tid >> 5;
    const int wl     = tid & 31;
    const int half   = wl >> 4;
    const int l16    = wl & 15;
    float* myx = sx[warpId];

    // half-bin work assignment: CTA b -> bin b>>1, half b&1
    const int w    = blockIdx.x >> 1;
    const int hsel = blockIdx.x & 1;
    const int cnt  = g_tot[w];
    const int h0   = (cnt + 1) >> 1;
    const int start = g_offsets[w] + (hsel ? h0 : 0);
    const int count = hsel ? (cnt - h0) : h0;

    float wr[D];
    {
        const float4* wr4 = reinterpret_cast<const float4*>(
            weight + (size_t)w * (D * D) + l16 * D);
        const float4 a = __ldg(&wr4[0]);
        const float4 b = __ldg(&wr4[1]);
        const float4 c = __ldg(&wr4[2]);
        const float4 d = __ldg(&wr4[3]);
        wr[0]=a.x;  wr[1]=a.y;  wr[2]=a.z;  wr[3]=a.w;
        wr[4]=b.x;  wr[5]=b.y;  wr[6]=b.z;  wr[7]=b.w;
        wr[8]=c.x;  wr[9]=c.y;  wr[10]=c.z; wr[11]=c.w;
        wr[12]=d.x; wr[13]=d.y; wr[14]=d.z; wr[15]=d.w;
    }

    const int b0 = warpId * 32;
    const int nfull = (count >= b0 + 32) ? ((count - b0 - 32) / 256 + 1) : 0;
    const int pbase = b0 + nfull * 256;

    if (nfull > 0) {
        int2 pe_cur, pe_nxt, pe_fut;
        pe_cur = g_pe[start + b0 + wl];

        // prologue: gather tile 0 into regs, prefetch pe(1), stage tile 0
        {
            float gx[16];
#pragma unroll
            for (int k = 0; k < 16; k++) {
                const int s  = 2 * k + half;
                const int ii = __shfl_sync(0xFFFFFFFFu, pe_cur.y, s);
                gx[k] = __ldg(&values[(size_t)ii * D + l16]);
            }
            if (nfull > 1) pe_nxt = g_pe[start + b0 + 256 + wl];
#pragma unroll
            for (int k = 0; k < 16; k++)
                myx[(2 * k + half) * D + l16] = gx[k];
        }
        __syncwarp();

        for (int j = 0; j < nfull; j++) {
            const bool hasN = (j + 1 < nfull);
            if (j + 2 < nfull) pe_fut = g_pe[start + b0 + (j + 2) * 256 + wl];

            // issue next tile's gathers (consumed only after compute)
            float gx[16];
            if (hasN) {
#pragma unroll
                for (int k = 0; k < 16; k++) {
                    const int s  = 2 * k + half;
                    const int ii = __shfl_sync(0xFFFFFFFFu, pe_nxt.y, s);
                    gx[k] = __ldg(&values[(size_t)ii * D + l16]);
                }
            }

            // compute current tile from smem (hides the loads above)
#pragma unroll
            for (int k = 0; k < 16; k++) {
                const int s = 2 * k + half;
                const float4* xr = reinterpret_cast<const float4*>(myx + s * D);
                const float4 x0 = xr[0];
                const float4 x1 = xr[1];
                const float4 x2 = xr[2];
                const float4 x3 = xr[3];
                float acc;
                MATVEC16(acc, wr, x0, x1, x2, x3);
                const int e = __shfl_sync(0xFFFFFFFFu, pe_cur.x, s);
                out[(size_t)e * D + l16] = acc;
            }
            __syncwarp();

            if (hasN) {
#pragma unroll
                for (int k = 0; k < 16; k++)
                    myx[(2 * k + half) * D + l16] = gx[k];
            }
            __syncwarp();

            pe_cur = pe_nxt;
            pe_nxt = pe_fut;
        }
    }

    // partial tail tile; shfls unconditional, memory ops predicated
    if (pbase < count) {
        const int nvalid = count - pbase;        // 1..31
        const int r = pbase + wl;
        const int2 pe = (r < count) ? g_pe[start + r] : make_int2(0, 0);

#pragma unroll
        for (int k = 0; k < 16; k++) {
            const int s  = 2 * k + half;
            const int ss = (s < nvalid) ? s : 0;
            const int ii = __shfl_sync(0xFFFFFFFFu, pe.y, ss);
            myx[s * D + l16] = __ldg(&values[(size_t)ii * D + l16]);
        }
        __syncwarp();

#pragma unroll
        for (int k = 0; k < 16; k++) {
            const int s  = 2 * k + half;
            const int ss = (s < nvalid) ? s : 0;
            const int e  = __shfl_sync(0xFFFFFFFFu, pe.x, ss);
            const float4* xr = reinterpret_cast<const float4*>(myx + s * D);
            const float4 x0 = xr[0];
            const float4 x1 = xr[1];
            const float4 x2 = xr[2];
            const float4 x3 = xr[3];
            float acc;
            MATVEC16(acc, wr, x0, x1, x2, x3);
            if (s < nvalid) out[(size_t)e * D + l16] = acc;
        }
        __syncwarp();
    }
}

// ---------------- fallback (R1 kernel) for unexpected shapes ----------------

__global__ __launch_bounds__(256) void edge_linear_fallback(
    const float* __restrict__ values,
    const float4* __restrict__ weight4,
    const int* __restrict__ input_idx,
    const int* __restrict__ weight_idx,
    float* __restrict__ out, int E)
{
    const int gtid = blockIdx.x * blockDim.x + threadIdx.x;
    const int edge = gtid >> 4;
    const int lane = threadIdx.x & 15;
    if (edge >= E) return;

    const int ii = __ldg(&input_idx[edge]);
    const int wi = __ldg(&weight_idx[edge]);
    const float xl = __ldg(&values[(size_t)ii * D + lane]);

    const float4* wrp = weight4 + (size_t)wi * (D * D / 4) + lane * 4;
    const float4 a = __ldg(&wrp[0]);
    const float4 b = __ldg(&wrp[1]);
    const float4 c = __ldg(&wrp[2]);
    const float4 d = __ldg(&wrp[3]);
    const float wrow[D] = {a.x, a.y, a.z, a.w,
                           b.x, b.y, b.z, b.w,
                           c.x, c.y, c.z, c.w,
                           d.x, d.y, d.z, d.w};

    float acc = 0.0f;
#pragma unroll
    for (int i = 0; i < D; i++)
        acc = fmaf(wrow[i], __shfl_sync(0xFFFFFFFFu, xl, i, 16), acc);

    out[(size_t)edge * D + lane] = acc;
}

extern "C" void kernel_launch(void* const* d_in, const int* in_sizes, int n_in,
                              void* d_out, int out_size)
{
    const float* values     = (const float*)d_in[0];
    const float* weight     = (const float*)d_in[1];
    const int*   input_idx  = (const int*)d_in[2];
    const int*   weight_idx = (const int*)d_in[3];
    float*       out        = (float*)d_out;

    const int E  = in_sizes[2];
    const int NW = in_sizes[1] / (D * D);

    const int chunk = (E + B_SORT - 1) / B_SORT;

    // rank must fit 12 bits of the packed word
    if (NW != NW_MAX || E > PERM_CAP || chunk > 4095) {
        const int threads = 256;
        const long long total = (long long)E * 16;
        edge_linear_fallback<<<(int)((total + threads - 1) / threads), threads>>>(
            values, (const float4*)weight, input_idx, weight_idx, out, E);
        return;
    }

    passA_hist        <<<B_SORT, T_SORT>>>(weight_idx, E, chunk);
    passB_colscan     <<<dim3(NW_MAX / 256, NSEG), 256>>>(B_SORT);
    passC_scan_scatter<<<B_SORT, T_SORT>>>(input_idx, E, chunk);
    compute_sorted_kernel<<<2 * NW_MAX, 256>>>(values, weight, out);
}